// round 3
// baseline (speedup 1.0000x reference)
#include <cuda_runtime.h>
#include <math.h>

#define Nn   12288
#define Ee   393216
#define Bb   16
#define FIN  15
#define Hh   32
#define H2   64
#define EMBD 64
#define NC   11

// ---------------- scratch (static device globals; no allocs) ----------------
__device__ float g_ew[Ee];
__device__ int   g_cnt[Nn];
__device__ int   g_rowptr[Nn + 1];
__device__ int   g_woff[Nn];
__device__ float g_deg[Nn];
__device__ float g_dis[Nn];
__device__ int   g_ccol[Ee];
__device__ float g_cval[Ee];

__device__ float g_bufA[Nn * 64];
__device__ float g_bufB[Nn * 64];
__device__ float g_bufC[Nn * 64];

__device__ float g_mu[64];
__device__ float g_inv[64];

__device__ float g_emb[Bb * EMBD];
__device__ float g_fc1[Bb * 512];
__device__ float g_fc2[Bb * 256];
__device__ float g_logits[Bb * NC];

// ---------------- preprocessing ----------------
__global__ void k_init() {
    int i = blockIdx.x * blockDim.x + threadIdx.x;
    if (i < Nn) { g_cnt[i] = 0; g_deg[i] = 0.f; g_woff[i] = 0; }
}

__global__ void k_edge(const float* __restrict__ ea, const float* __restrict__ we,
                       const float* __restrict__ be, const int* __restrict__ ei) {
    int e = blockIdx.x * blockDim.x + threadIdx.x;
    if (e >= Ee) return;
    float t = ea[2 * e] * we[0] + ea[2 * e + 1] * we[1] + be[0];
    float w = 1.f / (1.f + __expf(-t));
    g_ew[e] = w;
    int r = ei[e];  // edge_index[0][e]
    atomicAdd(&g_cnt[r], 1);
    atomicAdd(&g_deg[r], w);
}

// single-block exclusive scan of g_cnt -> g_rowptr (N = 1024 * 12 exactly)
__global__ void k_scan() {
    __shared__ int sh[1024];
    int t = threadIdx.x;
    const int C = Nn / 1024;  // 12
    int base = t * C;
    int pre[C];
    int s = 0;
    #pragma unroll
    for (int c = 0; c < C; c++) { pre[c] = s; s += g_cnt[base + c]; }
    sh[t] = s;
    __syncthreads();
    // Hillis-Steele inclusive scan
    for (int d = 1; d < 1024; d <<= 1) {
        int v = (t >= d) ? sh[t - d] : 0;
        __syncthreads();
        sh[t] += v;
        __syncthreads();
    }
    int off = (t > 0) ? sh[t - 1] : 0;
    #pragma unroll
    for (int c = 0; c < C; c++) g_rowptr[base + c] = off + pre[c];
    if (t == 1023) g_rowptr[Nn] = sh[1023];
}

__global__ void k_scatter(const int* __restrict__ ei) {
    int e = blockIdx.x * blockDim.x + threadIdx.x;
    if (e >= Ee) return;
    int r = ei[e];
    int c = ei[Ee + e];
    int p = g_rowptr[r] + atomicAdd(&g_woff[r], 1);
    g_ccol[p] = c;
    g_cval[p] = g_ew[e];
}

__global__ void k_dis() {
    int i = blockIdx.x * blockDim.x + threadIdx.x;
    if (i < Nn) g_dis[i] = rsqrtf(1.f + g_deg[i]);
}

__global__ void k_scale() {
    int p = blockIdx.x * blockDim.x + threadIdx.x;
    if (p < Ee) g_cval[p] *= g_dis[g_ccol[p]];
}

// ---------------- SpMM: out[i,:] = dis_i * (dis_i*in[i,:] + sum_k val_k * in[col_k,:]) ----
template <int F>
__global__ void k_spmm(const float* __restrict__ in, float* __restrict__ out) {
    int warp = (blockIdx.x * blockDim.x + threadIdx.x) >> 5;
    int lane = threadIdx.x & 31;
    if (warp >= Nn) return;
    int row = warp;
    float d = g_dis[row];
    int s = g_rowptr[row], e = g_rowptr[row + 1];
    if (F <= 32) {
        float acc = (lane < F) ? d * in[row * F + lane] : 0.f;
        for (int k = s; k < e; k++) {
            int   c = __ldg(&g_ccol[k]);
            float v = __ldg(&g_cval[k]);
            if (lane < F) acc += v * in[c * F + lane];
        }
        if (lane < F) out[row * F + lane] = d * acc;
    } else {
        float a0 = d * in[row * F + lane];
        float a1 = d * in[row * F + lane + 32];
        for (int k = s; k < e; k++) {
            int   c = __ldg(&g_ccol[k]);
            float v = __ldg(&g_cval[k]);
            a0 += v * in[c * F + lane];
            a1 += v * in[c * F + lane + 32];
        }
        out[row * F + lane]      = d * a0;
        out[row * F + lane + 32] = d * a1;
    }
}

// ---------------- dense GEMM for node matrices (W cached in shared) ----------------
__global__ void k_gemm(const float* __restrict__ in, const float* __restrict__ W,
                       const float* __restrict__ b, float* __restrict__ out,
                       int K, int Fo) {
    __shared__ float sW[64 * 64];
    int tot = K * Fo;
    for (int i = threadIdx.x; i < tot; i += blockDim.x) sW[i] = W[i];
    __syncthreads();
    int idx = blockIdx.x * blockDim.x + threadIdx.x;
    if (idx >= Nn * Fo) return;
    int i = idx / Fo, o = idx % Fo;
    float acc = b[o];
    const float* xi = in + i * K;
    for (int k = 0; k < K; k++) acc += xi[k] * sW[k * Fo + o];
    out[idx] = acc;
}

// ---------------- BatchNorm over N rows ----------------
__global__ void k_bnstats(const float* __restrict__ z, int F) {
    int c = blockIdx.x;
    int t = threadIdx.x;
    __shared__ float s1[256], s2[256];
    float a = 0.f, q = 0.f;
    for (int i = t; i < Nn; i += 256) {
        float v = z[i * F + c];
        a += v; q += v * v;
    }
    s1[t] = a; s2[t] = q;
    __syncthreads();
    for (int d = 128; d > 0; d >>= 1) {
        if (t < d) { s1[t] += s1[t + d]; s2[t] += s2[t + d]; }
        __syncthreads();
    }
    if (t == 0) {
        float mu  = s1[0] * (1.f / Nn);
        float var = s2[0] * (1.f / Nn) - mu * mu;
        g_mu[c]  = mu;
        g_inv[c] = rsqrtf(var + 1e-5f);
    }
}

__global__ void k_bnrelu(float* __restrict__ z, const float* __restrict__ g,
                         const float* __restrict__ be, int F) {
    int idx = blockIdx.x * blockDim.x + threadIdx.x;
    if (idx >= Nn * F) return;
    int c = idx % F;
    float v = g[c] * (z[idx] - g_mu[c]) * g_inv[c] + be[c];
    z[idx] = fmaxf(v, 0.f);
}

// ---------------- global max pool ----------------
__global__ void k_poolinit() {
    int j = blockIdx.x * blockDim.x + threadIdx.x;
    if (j < Bb * EMBD) g_emb[j] = 0.f;
}

__global__ void k_pool(const float* __restrict__ h, const int* __restrict__ batch) {
    int idx = blockIdx.x * blockDim.x + threadIdx.x;
    if (idx >= Nn * EMBD) return;
    int i = idx >> 6, f = idx & 63;
    int b = batch[i];
    float v = h[idx];           // post-ReLU => v >= 0, int-compare valid
    atomicMax((int*)&g_emb[b * EMBD + f], __float_as_int(v));
}

__global__ void k_copyemb(float* __restrict__ out) {
    int j = blockIdx.x * blockDim.x + threadIdx.x;
    if (j < Bb * EMBD) out[Bb * NC + j] = g_emb[j];
}

// ---------------- MLP head (tiny) ----------------
__global__ void k_gemm_g(const float* __restrict__ in, const float* __restrict__ W,
                         const float* __restrict__ b, float* __restrict__ out,
                         int M, int K, int Fo) {
    int idx = blockIdx.x * blockDim.x + threadIdx.x;
    if (idx >= M * Fo) return;
    int i = idx / Fo, o = idx % Fo;
    float acc = b[o];
    for (int k = 0; k < K; k++) acc += in[i * K + k] * W[k * Fo + o];
    out[idx] = acc;
}

__global__ void k_bn_small(float* __restrict__ z, const float* __restrict__ g,
                           const float* __restrict__ be, int F) {
    int c = blockIdx.x * blockDim.x + threadIdx.x;
    if (c >= F) return;
    float a = 0.f, q = 0.f;
    for (int i = 0; i < Bb; i++) {
        float v = z[i * F + c];
        a += v; q += v * v;
    }
    float mu  = a * (1.f / Bb);
    float var = q * (1.f / Bb) - mu * mu;
    float inv = rsqrtf(var + 1e-5f);
    for (int i = 0; i < Bb; i++) {
        float v = g[c] * (z[i * F + c] - mu) * inv + be[c];
        z[i * F + c] = fmaxf(v, 0.f);
    }
}

__global__ void k_logsoftmax(float* __restrict__ out) {
    int r = threadIdx.x;
    if (r >= Bb) return;
    float m = -1e30f;
    for (int j = 0; j < NC; j++) m = fmaxf(m, g_logits[r * NC + j]);
    float s = 0.f;
    for (int j = 0; j < NC; j++) s += expf(g_logits[r * NC + j] - m);
    float l = m + logf(s);
    for (int j = 0; j < NC; j++) out[r * NC + j] = g_logits[r * NC + j] - l;
}

// ---------------- launcher ----------------
extern "C" void kernel_launch(void* const* d_in, const int* in_sizes, int n_in,
                              void* d_out, int out_size) {
    const float* x        = (const float*)d_in[0];   // [N,15]
    const float* ea       = (const float*)d_in[1];   // [E,2]
    const float* w_edge   = (const float*)d_in[2];
    const float* b_edge   = (const float*)d_in[3];
    const float* w1  = (const float*)d_in[4];  const float* b1  = (const float*)d_in[5];
    const float* g1  = (const float*)d_in[6];  const float* be1 = (const float*)d_in[7];
    const float* w2  = (const float*)d_in[8];  const float* b2  = (const float*)d_in[9];
    const float* g2  = (const float*)d_in[10]; const float* be2 = (const float*)d_in[11];
    const float* w3  = (const float*)d_in[12]; const float* b3  = (const float*)d_in[13];
    const float* g3  = (const float*)d_in[14]; const float* be3 = (const float*)d_in[15];
    const float* wf1 = (const float*)d_in[16]; const float* bf1 = (const float*)d_in[17];
    const float* gf1 = (const float*)d_in[18]; const float* bef1= (const float*)d_in[19];
    const float* wf2 = (const float*)d_in[20]; const float* bf2 = (const float*)d_in[21];
    const float* gf2 = (const float*)d_in[22]; const float* bef2= (const float*)d_in[23];
    const float* wf3 = (const float*)d_in[24]; const float* bf3 = (const float*)d_in[25];
    const int*   ei    = (const int*)d_in[26];       // [2,E]
    const int*   batch = (const int*)d_in[27];       // [N]
    float* out = (float*)d_out;

    float *bufA, *bufB, *bufC, *emb, *fc1, *fc2, *logits;
    cudaGetSymbolAddress((void**)&bufA,   g_bufA);
    cudaGetSymbolAddress((void**)&bufB,   g_bufB);
    cudaGetSymbolAddress((void**)&bufC,   g_bufC);
    cudaGetSymbolAddress((void**)&emb,    g_emb);
    cudaGetSymbolAddress((void**)&fc1,    g_fc1);
    cudaGetSymbolAddress((void**)&fc2,    g_fc2);
    cudaGetSymbolAddress((void**)&logits, g_logits);

    const int T = 256;
    // ---- graph preprocessing: ew, degree, CSR, normalization ----
    k_init<<<(Nn + T - 1) / T, T>>>();
    k_edge<<<(Ee + T - 1) / T, T>>>(ea, w_edge, b_edge, ei);
    k_scan<<<1, 1024>>>();
    k_scatter<<<(Ee + T - 1) / T, T>>>(ei);
    k_dis<<<(Nn + T - 1) / T, T>>>();
    k_scale<<<(Ee + T - 1) / T, T>>>();

    const int SPMM_GRID = (Nn * 32 + T - 1) / T;  // one warp per row

    // ---- GCN layer 1: F 15 -> 32 ----
    k_spmm<FIN><<<SPMM_GRID, T>>>(x, bufA);
    k_gemm<<<(Nn * Hh + T - 1) / T, T>>>(bufA, w1, b1, bufB, FIN, Hh);
    k_bnstats<<<Hh, 256>>>(bufB, Hh);
    k_bnrelu<<<(Nn * Hh + T - 1) / T, T>>>(bufB, g1, be1, Hh);

    // ---- GCN layer 2: F 32 -> 64 ----
    k_spmm<Hh><<<SPMM_GRID, T>>>(bufB, bufA);
    k_gemm<<<(Nn * H2 + T - 1) / T, T>>>(bufA, w2, b2, bufC, Hh, H2);
    k_bnstats<<<H2, 256>>>(bufC, H2);
    k_bnrelu<<<(Nn * H2 + T - 1) / T, T>>>(bufC, g2, be2, H2);

    // ---- GCN layer 3: F 64 -> 64 ----
    k_spmm<H2><<<SPMM_GRID, T>>>(bufC, bufA);
    k_gemm<<<(Nn * EMBD + T - 1) / T, T>>>(bufA, w3, b3, bufB, H2, EMBD);
    k_bnstats<<<EMBD, 256>>>(bufB, EMBD);
    k_bnrelu<<<(Nn * EMBD + T - 1) / T, T>>>(bufB, g3, be3, EMBD);

    // ---- global max pool ----
    k_poolinit<<<(Bb * EMBD + T - 1) / T, T>>>();
    k_pool<<<(Nn * EMBD + T - 1) / T, T>>>(bufB, batch);
    if (out_size >= Bb * NC + Bb * EMBD)
        k_copyemb<<<(Bb * EMBD + T - 1) / T, T>>>(out);

    // ---- MLP head ----
    k_gemm_g<<<(Bb * 512 + T - 1) / T, T>>>(emb, wf1, bf1, fc1, Bb, EMBD, 512);
    k_bn_small<<<(512 + T - 1) / T, T>>>(fc1, gf1, bef1, 512);
    k_gemm_g<<<(Bb * 256 + T - 1) / T, T>>>(fc1, wf2, bf2, fc2, Bb, 512, 256);
    k_bn_small<<<(256 + T - 1) / T, T>>>(fc2, gf2, bef2, 256);
    k_gemm_g<<<(Bb * NC + T - 1) / T, T>>>(fc2, wf3, bf3, logits, Bb, 256, NC);
    k_logsoftmax<<<1, 32>>>(out);
}

// round 4
// speedup vs baseline: 1.3857x; 1.3857x over previous
#include <cuda_runtime.h>
#include <math.h>

#define Nn   12288
#define Ee   393216
#define Bb   16
#define FIN  15
#define Hh   32
#define H2   64
#define EMBD 64
#define NC   11

// ---------------- scratch (static device globals; no allocs) ----------------
__device__ float  g_ew[Ee];
__device__ int    g_cnt[Nn];
__device__ int    g_rowptr[Nn + 1];
__device__ int    g_woff[Nn];
__device__ float  g_deg[Nn];
__device__ float2 g_pack[Ee];          // (col bits, val = ew * dis[col])

__device__ float g_z1[Nn * Hh];        // layer1 raw gemm output
__device__ float g_z2[Nn * H2];        // layer2 raw
__device__ float g_z3[Nn * H2];        // layer3 raw

__device__ float g_sum[3 * 64];        // BN stats accumulators (layer l at l*64)
__device__ float g_sq [3 * 64];

__device__ float g_emb[Bb * EMBD];
__device__ float g_fc1[Bb * 512];
__device__ float g_fc2[Bb * 256];

// ---------------- preprocessing ----------------
__global__ void k_init() {
    int i = blockIdx.x * blockDim.x + threadIdx.x;
    if (i < Nn) { g_cnt[i] = 0; g_woff[i] = 0; g_deg[i] = 0.f; }
    if (i < 3 * 64) { g_sum[i] = 0.f; g_sq[i] = 0.f; }
    if (i < Bb * EMBD) g_emb[i] = 0.f;
}

__global__ void k_edge(const float* __restrict__ ea, const float* __restrict__ we,
                       const float* __restrict__ be, const int* __restrict__ ei) {
    int e = blockIdx.x * blockDim.x + threadIdx.x;
    if (e >= Ee) return;
    float2 a = ((const float2*)ea)[e];
    float t = a.x * we[0] + a.y * we[1] + be[0];
    float w = 1.f / (1.f + __expf(-t));
    g_ew[e] = w;
    int r = ei[e];
    atomicAdd(&g_cnt[r], 1);
    atomicAdd(&g_deg[r], w);
}

// single-block exclusive scan of g_cnt -> g_rowptr (N = 1024 * 12 exactly)
__global__ void k_scan() {
    __shared__ int sh[1024];
    int t = threadIdx.x;
    const int C = Nn / 1024;  // 12
    int base = t * C;
    int pre[C];
    int s = 0;
    #pragma unroll
    for (int c = 0; c < C; c++) { pre[c] = s; s += g_cnt[base + c]; }
    sh[t] = s;
    __syncthreads();
    for (int d = 1; d < 1024; d <<= 1) {
        int v = (t >= d) ? sh[t - d] : 0;
        __syncthreads();
        sh[t] += v;
        __syncthreads();
    }
    int off = (t > 0) ? sh[t - 1] : 0;
    #pragma unroll
    for (int c = 0; c < C; c++) g_rowptr[base + c] = off + pre[c];
    if (t == 1023) g_rowptr[Nn] = sh[1023];
}

__global__ void k_scatter(const int* __restrict__ ei) {
    int e = blockIdx.x * blockDim.x + threadIdx.x;
    if (e >= Ee) return;
    int r = ei[e];
    int c = ei[Ee + e];
    float val = g_ew[e] * rsqrtf(1.f + g_deg[c]);   // fold dis[col] into edge value
    int p = g_rowptr[r] + atomicAdd(&g_woff[r], 1);
    g_pack[p] = make_float2(__int_as_float(c), val);
}

// ---------------- fused GCN layer: (BN+ReLU of prev) -> SpMM -> GEMM -> BN stats ----
template <int FI, int FO, bool BN_IN, int GRID>
__global__ void __launch_bounds__(256) k_layer(
    const float* __restrict__ in,        // [N,FI] raw (pre-BN if BN_IN)
    const float* __restrict__ W,         // [FI,FO]
    const float* __restrict__ bias,      // [FO]
    const float* __restrict__ gam, const float* __restrict__ bet,       // prev-layer BN
    const float* __restrict__ sum_in, const float* __restrict__ sq_in,  // prev stats
    float* __restrict__ out,             // [N,FO] raw
    float* __restrict__ sum_out, float* __restrict__ sq_out)
{
    __shared__ float sW[FI * FO];
    __shared__ float sRow[8][FI];
    __shared__ float sScale[FI], sShift[FI];
    __shared__ float sSum[FO], sSq[FO];
    int tid = threadIdx.x;
    for (int i = tid; i < FI * FO; i += 256) sW[i] = W[i];
    if (tid < FO) { sSum[tid] = 0.f; sSq[tid] = 0.f; }
    if (BN_IN && tid < FI) {
        float mu  = sum_in[tid] * (1.f / (float)Nn);
        float var = sq_in[tid]  * (1.f / (float)Nn) - mu * mu;
        float inv = rsqrtf(var + 1e-5f);
        float sc  = gam[tid] * inv;
        sScale[tid] = sc;
        sShift[tid] = bet[tid] - sc * mu;
    }
    __syncthreads();

    int warp = tid >> 5, lane = tid & 31;
    float b0 = (lane < FO) ? bias[lane] : 0.f;
    float b1 = (FO > 32) ? bias[lane + 32] : 0.f;
    float sc0 = 1.f, sh0 = 0.f, sc1 = 1.f, sh1 = 0.f;
    if (BN_IN) {
        if (lane < FI) { sc0 = sScale[lane]; sh0 = sShift[lane]; }
        if (FI > 32)   { sc1 = sScale[lane + 32]; sh1 = sShift[lane + 32]; }
    }

    const int RPW = Nn / (GRID * 8);
    int rowBase = (blockIdx.x * 8 + warp) * RPW;
    for (int rr = 0; rr < RPW; rr++) {
        int row = rowBase + rr;
        float d = rsqrtf(1.f + g_deg[row]);
        int s = g_rowptr[row], e = g_rowptr[row + 1];
        float a0 = 0.f, a1 = 0.f;
        // self-loop term (weight 1)
        if (lane < FI) {
            float v = in[row * FI + lane];
            if (BN_IN) v = fmaxf(sc0 * v + sh0, 0.f);
            a0 = d * v;
        }
        if (FI > 32) {
            float v = in[row * FI + lane + 32];
            if (BN_IN) v = fmaxf(sc1 * v + sh1, 0.f);
            a1 = d * v;
        }
        for (int k = s; k < e; k++) {
            float2 p = __ldg(&g_pack[k]);     // broadcast: one 8B load/warp
            int   c = __float_as_int(p.x);
            float w = p.y;
            if (lane < FI) {
                float v = in[c * FI + lane];
                if (BN_IN) v = fmaxf(sc0 * v + sh0, 0.f);
                a0 += w * v;
            }
            if (FI > 32) {
                float v = in[c * FI + lane + 32];
                if (BN_IN) v = fmaxf(sc1 * v + sh1, 0.f);
                a1 += w * v;
            }
        }
        a0 *= d; a1 *= d;
        __syncwarp();
        if (lane < FI) sRow[warp][lane] = a0;
        if (FI > 32)   sRow[warp][lane + 32] = a1;
        __syncwarp();
        // in-warp GEMM against shared W
        float o0 = b0, o1 = b1;
        #pragma unroll
        for (int f = 0; f < FI; f++) {
            float h = sRow[warp][f];
            o0 += h * sW[f * FO + lane];
            if (FO > 32) o1 += h * sW[f * FO + lane + 32];
        }
        if (lane < FO) {
            out[row * FO + lane] = o0;
            atomicAdd(&sSum[lane], o0);
            atomicAdd(&sSq[lane],  o0 * o0);
        }
        if (FO > 32) {
            out[row * FO + lane + 32] = o1;
            atomicAdd(&sSum[lane + 32], o1);
            atomicAdd(&sSq[lane + 32],  o1 * o1);
        }
    }
    __syncthreads();
    if (tid < FO) {
        atomicAdd(&sum_out[tid], sSum[tid]);
        atomicAdd(&sq_out[tid],  sSq[tid]);
    }
}

// ---------------- global max pool with inline BN3+ReLU ----------------
__global__ void k_pool(const float* __restrict__ z3, const int* __restrict__ batch,
                       const float* __restrict__ gam, const float* __restrict__ bet) {
    __shared__ float scl[64], shf[64];
    if (threadIdx.x < 64) {
        int f = threadIdx.x;
        float mu  = g_sum[128 + f] * (1.f / (float)Nn);
        float var = g_sq [128 + f] * (1.f / (float)Nn) - mu * mu;
        float inv = rsqrtf(var + 1e-5f);
        float sc  = gam[f] * inv;
        scl[f] = sc; shf[f] = bet[f] - sc * mu;
    }
    __syncthreads();
    int idx = blockIdx.x * blockDim.x + threadIdx.x;
    if (idx >= Nn * 64) return;
    int i = idx >> 6, f = idx & 63;
    float v = fmaxf(scl[f] * z3[idx] + shf[f], 0.f);   // >= 0 -> int compare valid
    atomicMax((int*)&g_emb[batch[i] * 64 + f], __float_as_int(v));
}

// ---------------- MLP head: 3 fused kernels ----------------
// fc1 (16x64 @ 64x512) + BN + ReLU.  grid = 8 blocks x 64 cols.
__global__ void __launch_bounds__(256) k_mlp1(
    const float* __restrict__ wf1, const float* __restrict__ bf1,
    const float* __restrict__ gf1, const float* __restrict__ bef1,
    float* __restrict__ out) {
    __shared__ float se[16 * 64];
    __shared__ float sz[16][64];
    __shared__ float scl[64], shf[64];
    int t = threadIdx.x;
    for (int i = t; i < 1024; i += 256) se[i] = g_emb[i];
    __syncthreads();
    int cl = t & 63;
    int r0 = t >> 6;                 // 0..3
    int c = blockIdx.x * 64 + cl;
    #pragma unroll
    for (int q = 0; q < 4; q++) {
        int r = r0 + q * 4;
        float a0 = 0.f, a1 = 0.f, a2 = 0.f, a3 = 0.f;
        #pragma unroll
        for (int k = 0; k < 64; k += 4) {
            a0 += se[r * 64 + k]     * wf1[(k)     * 512 + c];
            a1 += se[r * 64 + k + 1] * wf1[(k + 1) * 512 + c];
            a2 += se[r * 64 + k + 2] * wf1[(k + 2) * 512 + c];
            a3 += se[r * 64 + k + 3] * wf1[(k + 3) * 512 + c];
        }
        sz[r][cl] = bf1[c] + ((a0 + a1) + (a2 + a3));
    }
    __syncthreads();
    if (t < 64) {
        float s = 0.f, q = 0.f;
        for (int r = 0; r < 16; r++) { float v = sz[r][t]; s += v; q += v * v; }
        float mu = s * (1.f / Bb), var = q * (1.f / Bb) - mu * mu;
        float inv = rsqrtf(var + 1e-5f);
        float sc = gf1[blockIdx.x * 64 + t] * inv;
        scl[t] = sc; shf[t] = bef1[blockIdx.x * 64 + t] - sc * mu;
    }
    __syncthreads();
    #pragma unroll
    for (int q = 0; q < 4; q++) {
        int r = r0 + q * 4;
        g_fc1[r * 512 + c] = fmaxf(scl[cl] * sz[r][cl] + shf[cl], 0.f);
    }
    if (blockIdx.x == 0)             // copy emb -> out (after pool; reference order)
        for (int i = t; i < 1024; i += 256) out[Bb * NC + i] = se[i];
}

// fc2 (16x512 @ 512x256) + BN + ReLU.  grid = 8 blocks x 32 cols.
__global__ void __launch_bounds__(256) k_mlp2(
    const float* __restrict__ wf2, const float* __restrict__ bf2,
    const float* __restrict__ gf2, const float* __restrict__ bef2) {
    __shared__ float sf[16 * 512];
    __shared__ float sz[16][32];
    __shared__ float scl[32], shf[32];
    int t = threadIdx.x;
    for (int i = t; i < 8192; i += 256) sf[i] = g_fc1[i];
    __syncthreads();
    int cl = t & 31;
    int r0 = t >> 5;                 // 0..7
    int c = blockIdx.x * 32 + cl;
    #pragma unroll
    for (int q = 0; q < 2; q++) {
        int r = r0 + q * 8;
        float a0 = 0.f, a1 = 0.f, a2 = 0.f, a3 = 0.f;
        for (int k = 0; k < 512; k += 4) {
            a0 += sf[r * 512 + k]     * wf2[(k)     * 256 + c];
            a1 += sf[r * 512 + k + 1] * wf2[(k + 1) * 256 + c];
            a2 += sf[r * 512 + k + 2] * wf2[(k + 2) * 256 + c];
            a3 += sf[r * 512 + k + 3] * wf2[(k + 3) * 256 + c];
        }
        sz[r][cl] = bf2[c] + ((a0 + a1) + (a2 + a3));
    }
    __syncthreads();
    if (t < 32) {
        float s = 0.f, q = 0.f;
        for (int r = 0; r < 16; r++) { float v = sz[r][t]; s += v; q += v * v; }
        float mu = s * (1.f / Bb), var = q * (1.f / Bb) - mu * mu;
        float inv = rsqrtf(var + 1e-5f);
        float sc = gf2[blockIdx.x * 32 + t] * inv;
        scl[t] = sc; shf[t] = bef2[blockIdx.x * 32 + t] - sc * mu;
    }
    __syncthreads();
    #pragma unroll
    for (int q = 0; q < 2; q++) {
        int r = r0 + q * 8;
        g_fc2[r * 256 + c] = fmaxf(scl[cl] * sz[r][cl] + shf[cl], 0.f);
    }
}

// fc3 (16x256 @ 256x11) + log_softmax.  1 block.
__global__ void __launch_bounds__(256) k_mlp3(
    const float* __restrict__ wf3, const float* __restrict__ bf3,
    float* __restrict__ out) {
    __shared__ float sf[16 * 256];
    __shared__ float sl[16][11];
    int t = threadIdx.x;
    for (int i = t; i < 4096; i += 256) sf[i] = g_fc2[i];
    __syncthreads();
    if (t < Bb * NC) {
        int r = t / NC, j = t % NC;
        float a0 = 0.f, a1 = 0.f, a2 = 0.f, a3 = 0.f;
        for (int k = 0; k < 256; k += 4) {
            a0 += sf[r * 256 + k]     * wf3[(k)     * NC + j];
            a1 += sf[r * 256 + k + 1] * wf3[(k + 1) * NC + j];
            a2 += sf[r * 256 + k + 2] * wf3[(k + 2) * NC + j];
            a3 += sf[r * 256 + k + 3] * wf3[(k + 3) * NC + j];
        }
        sl[r][j] = bf3[j] + ((a0 + a1) + (a2 + a3));
    }
    __syncthreads();
    if (t < Bb) {
        float m = -1e30f;
        for (int j = 0; j < NC; j++) m = fmaxf(m, sl[t][j]);
        float s = 0.f;
        for (int j = 0; j < NC; j++) s += expf(sl[t][j] - m);
        float l = m + logf(s);
        for (int j = 0; j < NC; j++) out[t * NC + j] = sl[t][j] - l;
    }
}

// ---------------- launcher ----------------
extern "C" void kernel_launch(void* const* d_in, const int* in_sizes, int n_in,
                              void* d_out, int out_size) {
    const float* x      = (const float*)d_in[0];
    const float* ea     = (const float*)d_in[1];
    const float* w_edge = (const float*)d_in[2];
    const float* b_edge = (const float*)d_in[3];
    const float* w1  = (const float*)d_in[4];  const float* b1  = (const float*)d_in[5];
    const float* g1  = (const float*)d_in[6];  const float* be1 = (const float*)d_in[7];
    const float* w2  = (const float*)d_in[8];  const float* b2  = (const float*)d_in[9];
    const float* g2  = (const float*)d_in[10]; const float* be2 = (const float*)d_in[11];
    const float* w3  = (const float*)d_in[12]; const float* b3  = (const float*)d_in[13];
    const float* g3  = (const float*)d_in[14]; const float* be3 = (const float*)d_in[15];
    const float* wf1 = (const float*)d_in[16]; const float* bf1 = (const float*)d_in[17];
    const float* gf1 = (const float*)d_in[18]; const float* bef1= (const float*)d_in[19];
    const float* wf2 = (const float*)d_in[20]; const float* bf2 = (const float*)d_in[21];
    const float* gf2 = (const float*)d_in[22]; const float* bef2= (const float*)d_in[23];
    const float* wf3 = (const float*)d_in[24]; const float* bf3 = (const float*)d_in[25];
    const int*   ei    = (const int*)d_in[26];
    const int*   batch = (const int*)d_in[27];
    float* out = (float*)d_out;

    float *z1, *z2, *z3, *sum, *sq;
    cudaGetSymbolAddress((void**)&z1,  g_z1);
    cudaGetSymbolAddress((void**)&z2,  g_z2);
    cudaGetSymbolAddress((void**)&z3,  g_z3);
    cudaGetSymbolAddress((void**)&sum, g_sum);
    cudaGetSymbolAddress((void**)&sq,  g_sq);

    const int T = 256;
    // preprocessing: ew + degree -> rowptr -> packed CSR (dis folded)
    k_init<<<(Nn + T - 1) / T, T>>>();
    k_edge<<<(Ee + T - 1) / T, T>>>(ea, w_edge, b_edge, ei);
    k_scan<<<1, 1024>>>();
    k_scatter<<<(Ee + T - 1) / T, T>>>(ei);

    constexpr int LG = 768;  // 768 blocks * 8 warps * 2 rows = 12288
    k_layer<FIN, Hh, false, LG><<<LG, T>>>(x,  w1, b1, nullptr, nullptr, nullptr, nullptr,
                                           z1, sum,      sq);
    k_layer<Hh,  H2, true,  LG><<<LG, T>>>(z1, w2, b2, g1, be1, sum,      sq,
                                           z2, sum + 64, sq + 64);
    k_layer<H2,  H2, true,  LG><<<LG, T>>>(z2, w3, b3, g2, be2, sum + 64, sq + 64,
                                           z3, sum + 128, sq + 128);

    k_pool<<<(Nn * 64 + T - 1) / T, T>>>(z3, batch, g3, be3);

    k_mlp1<<<8, T>>>(wf1, bf1, gf1, bef1, out);
    k_mlp2<<<8, T>>>(wf2, bf2, gf2, bef2);
    k_mlp3<<<1, T>>>(wf3, bf3, out);
}

// round 6
// speedup vs baseline: 1.5360x; 1.1085x over previous
#include <cuda_runtime.h>
#include <math.h>

#define Nn   12288
#define Ee   393216
#define Bb   16
#define FIN  15
#define Hh   32
#define H2   64
#define NC   11

// ---------------- scratch (static device globals; no allocs) ----------------
__device__ float  g_ew[Ee];
__device__ int    g_cnt[Nn];
__device__ int    g_rowptr[Nn + 1];
__device__ int    g_woff[Nn];
__device__ float  g_deg[Nn];
__device__ float2 g_pack[Ee];          // (col bits, val = ew * dis[col])

__device__ float g_x16[Nn * 16];       // x padded 15 -> 16 for float4 gathers
__device__ float g_z1[Nn * Hh];
__device__ float g_z2[Nn * H2];
__device__ float g_z3[Nn * H2];

__device__ float g_sum[3 * 64];
__device__ float g_sq [3 * 64];

__device__ float g_emb[Bb * 64];
__device__ float g_fc1[Bb * 512];
__device__ float g_fc2[Bb * 256];

// ---------------- init + pad x ----------------
__global__ void k_init(const float* __restrict__ x) {
    int i = blockIdx.x * blockDim.x + threadIdx.x;
    if (i < Nn * 16) {
        int f = i & 15;
        g_x16[i] = (f < FIN) ? x[(i >> 4) * FIN + f] : 0.f;
    }
    if (i < Nn) { g_cnt[i] = 0; g_woff[i] = 0; g_deg[i] = 0.f; }
    if (i < 3 * 64) { g_sum[i] = 0.f; g_sq[i] = 0.f; }
    if (i < Bb * 64) g_emb[i] = 0.f;
}

__global__ void k_edge(const float* __restrict__ ea, const float* __restrict__ we,
                       const float* __restrict__ be, const int* __restrict__ ei) {
    int e = blockIdx.x * blockDim.x + threadIdx.x;
    if (e >= Ee) return;
    float2 a = ((const float2*)ea)[e];
    float t = a.x * we[0] + a.y * we[1] + be[0];
    float w = 1.f / (1.f + __expf(-t));
    g_ew[e] = w;
    int r = ei[e];
    atomicAdd(&g_cnt[r], 1);
    atomicAdd(&g_deg[r], w);
}

// single-block exclusive scan of g_cnt -> g_rowptr
__global__ void k_scan() {
    __shared__ int sh[1024];
    int t = threadIdx.x;
    const int C = Nn / 1024;  // 12
    int base = t * C;
    int pre[C];
    int s = 0;
    #pragma unroll
    for (int c = 0; c < C; c++) { pre[c] = s; s += g_cnt[base + c]; }
    sh[t] = s;
    __syncthreads();
    for (int d = 1; d < 1024; d <<= 1) {
        int v = (t >= d) ? sh[t - d] : 0;
        __syncthreads();
        sh[t] += v;
        __syncthreads();
    }
    int off = (t > 0) ? sh[t - 1] : 0;
    #pragma unroll
    for (int c = 0; c < C; c++) g_rowptr[base + c] = off + pre[c];
    if (t == 1023) g_rowptr[Nn] = sh[1023];
}

__global__ void k_scatter(const int* __restrict__ ei) {
    int e = blockIdx.x * blockDim.x + threadIdx.x;
    if (e >= Ee) return;
    int r = ei[e];
    int c = ei[Ee + e];
    float val = g_ew[e] * rsqrtf(1.f + g_deg[c]);
    int p = g_rowptr[r] + atomicAdd(&g_woff[r], 1);
    g_pack[p] = make_float2(__int_as_float(c), val);
}

// ---- fused GCN layer: (BN+ReLU of prev inline) -> SpMM -> GEMM -> BN stats ----
// Warp splits into EPW = 32/LPE edge slots, LPE = FI/4 lanes each; each slot
// gathers a full feature row as float4s in a single LDG.128 per step.
template <int FI, int FIeff, int FO, bool BN_IN, int GRID>
__global__ void __launch_bounds__(256) k_layer(
    const float* __restrict__ in,
    const float* __restrict__ W,         // [FIeff,FO]
    const float* __restrict__ bias,
    const float* __restrict__ gam, const float* __restrict__ bet,
    const float* __restrict__ sum_in, const float* __restrict__ sq_in,
    float* __restrict__ out,
    float* __restrict__ sum_out, float* __restrict__ sq_out)
{
    constexpr int LPE = FI / 4;
    constexpr int EPW = 32 / LPE;
    __shared__ float  sW[FIeff * FO];
    __shared__ float4 sRow4[8][16];
    __shared__ float  sScale[FI], sShift[FI];
    __shared__ float  sSum[FO], sSq[FO];
    int tid = threadIdx.x;
    for (int i = tid; i < FIeff * FO; i += 256) sW[i] = W[i];
    if (tid < FO) { sSum[tid] = 0.f; sSq[tid] = 0.f; }
    if (tid < FI) {
        if (BN_IN) {
            float mu  = sum_in[tid] * (1.f / (float)Nn);
            float var = sq_in[tid]  * (1.f / (float)Nn) - mu * mu;
            float inv = rsqrtf(var + 1e-5f);
            float sc  = gam[tid] * inv;
            sScale[tid] = sc;
            sShift[tid] = bet[tid] - sc * mu;
        } else { sScale[tid] = 1.f; sShift[tid] = 0.f; }
    }
    __syncthreads();

    int warp = tid >> 5, lane = tid & 31;
    int eh = lane / LPE;        // edge slot
    int fl = lane % LPE;        // feature quad
    float4 sc4, sh4;
    sc4.x = sScale[4*fl+0]; sc4.y = sScale[4*fl+1];
    sc4.z = sScale[4*fl+2]; sc4.w = sScale[4*fl+3];
    sh4.x = sShift[4*fl+0]; sh4.y = sShift[4*fl+1];
    sh4.z = sShift[4*fl+2]; sh4.w = sShift[4*fl+3];
    float b0 = (lane < FO) ? bias[lane] : 0.f;
    float b1 = (FO > 32) ? bias[lane + 32] : 0.f;

    const float4* in4 = (const float4*)in;
    const int RPW = Nn / (GRID * 8);
    int rowBase = (blockIdx.x * 8 + warp) * RPW;

    for (int rr = 0; rr < RPW; rr++) {
        int row = rowBase + rr;
        float d = rsqrtf(1.f + g_deg[row]);
        int s = g_rowptr[row], e = g_rowptr[row + 1];

        float4 acc = make_float4(0.f, 0.f, 0.f, 0.f);
        if (eh == 0) {   // self-loop (weight 1): d * bnrelu(in[row])
            float4 v = in4[row * LPE + fl];
            if (BN_IN) {
                v.x = fmaxf(fmaf(sc4.x, v.x, sh4.x), 0.f);
                v.y = fmaxf(fmaf(sc4.y, v.y, sh4.y), 0.f);
                v.z = fmaxf(fmaf(sc4.z, v.z, sh4.z), 0.f);
                v.w = fmaxf(fmaf(sc4.w, v.w, sh4.w), 0.f);
            }
            acc.x = d * v.x; acc.y = d * v.y; acc.z = d * v.z; acc.w = d * v.w;
        }

        for (int base = s; base < e; base += 32) {
            int n = min(32, e - base);
            float2 pk = (lane < n) ? __ldg(&g_pack[base + lane])
                                   : make_float2(__int_as_float(0), 0.f);
            for (int j = 0; j < n; j += EPW) {
                int src = j + eh;
                int   c = __float_as_int(__shfl_sync(0xffffffffu, pk.x, src));
                float w = __shfl_sync(0xffffffffu, pk.y, src);
                float4 v = in4[c * LPE + fl];
                if (BN_IN) {
                    v.x = fmaxf(fmaf(sc4.x, v.x, sh4.x), 0.f);
                    v.y = fmaxf(fmaf(sc4.y, v.y, sh4.y), 0.f);
                    v.z = fmaxf(fmaf(sc4.z, v.z, sh4.z), 0.f);
                    v.w = fmaxf(fmaf(sc4.w, v.w, sh4.w), 0.f);
                }
                acc.x = fmaf(w, v.x, acc.x);
                acc.y = fmaf(w, v.y, acc.y);
                acc.z = fmaf(w, v.z, acc.z);
                acc.w = fmaf(w, v.w, acc.w);
            }
        }
        // reduce over edge slots
        #pragma unroll
        for (int o = LPE; o < 32; o <<= 1) {
            acc.x += __shfl_xor_sync(0xffffffffu, acc.x, o);
            acc.y += __shfl_xor_sync(0xffffffffu, acc.y, o);
            acc.z += __shfl_xor_sync(0xffffffffu, acc.z, o);
            acc.w += __shfl_xor_sync(0xffffffffu, acc.w, o);
        }
        acc.x *= d; acc.y *= d; acc.z *= d; acc.w *= d;
        if (eh == 0) sRow4[warp][fl] = acc;
        __syncwarp();
        const float* h = (const float*)&sRow4[warp][0];
        float o0 = b0, o1 = b1;
        #pragma unroll
        for (int f = 0; f < FIeff; f++) {
            float hv = h[f];
            o0 = fmaf(hv, sW[f * FO + lane], o0);
            if (FO > 32) o1 = fmaf(hv, sW[f * FO + lane + 32], o1);
        }
        __syncwarp();
        if (lane < FO) {
            out[row * FO + lane] = o0;
            atomicAdd(&sSum[lane], o0);
            atomicAdd(&sSq[lane],  o0 * o0);
        }
        if (FO > 32) {
            out[row * FO + lane + 32] = o1;
            atomicAdd(&sSum[lane + 32], o1);
            atomicAdd(&sSq[lane + 32],  o1 * o1);
        }
    }
    __syncthreads();
    if (tid < FO) {
        atomicAdd(&sum_out[tid], sSum[tid]);
        atomicAdd(&sq_out[tid],  sSq[tid]);
    }
}

// ---------------- max pool: sorted-batch segment flush ----------------
// 96 blocks x 256 threads; block handles 128 rows; 64 threads share a row stream.
__global__ void __launch_bounds__(256) k_pool(
    const float* __restrict__ z3, const int* __restrict__ batch,
    const float* __restrict__ gam, const float* __restrict__ bet) {
    __shared__ float scl[64], shf[64];
    int t = threadIdx.x;
    if (t < 64) {
        float mu  = g_sum[128 + t] * (1.f / (float)Nn);
        float var = g_sq [128 + t] * (1.f / (float)Nn) - mu * mu;
        float inv = rsqrtf(var + 1e-5f);
        float sc  = gam[t] * inv;
        scl[t] = sc; shf[t] = bet[t] - sc * mu;
    }
    __syncthreads();
    int f  = t & 63;
    int r0 = blockIdx.x * 128 + (t >> 6);
    float sc = scl[f], sh = shf[f];
    int curb = -1; float cm = 0.f;
    for (int r = r0; r < blockIdx.x * 128 + 128; r += 4) {
        int b = batch[r];
        float v = fmaxf(fmaf(sc, z3[r * 64 + f], sh), 0.f);
        if (b != curb) {
            if (curb >= 0) atomicMax((int*)&g_emb[curb * 64 + f], __float_as_int(cm));
            curb = b; cm = v;
        } else cm = fmaxf(cm, v);
    }
    if (curb >= 0) atomicMax((int*)&g_emb[curb * 64 + f], __float_as_int(cm));
}

// ---------------- MLP head ----------------
__global__ void __launch_bounds__(256) k_mlp1(
    const float* __restrict__ wf1, const float* __restrict__ bf1,
    const float* __restrict__ gf1, const float* __restrict__ bef1,
    float* __restrict__ out) {
    __shared__ float se[16 * 64];
    __shared__ float sz[16][64];
    __shared__ float scl[64], shf[64];
    int t = threadIdx.x;
    for (int i = t; i < 1024; i += 256) se[i] = g_emb[i];
    __syncthreads();
    int cl = t & 63;
    int r0 = t >> 6;
    int c = blockIdx.x * 64 + cl;
    #pragma unroll
    for (int q = 0; q < 4; q++) {
        int r = r0 + q * 4;
        float a0 = 0.f, a1 = 0.f, a2 = 0.f, a3 = 0.f;
        #pragma unroll
        for (int k = 0; k < 64; k += 4) {
            a0 += se[r * 64 + k]     * wf1[(k)     * 512 + c];
            a1 += se[r * 64 + k + 1] * wf1[(k + 1) * 512 + c];
            a2 += se[r * 64 + k + 2] * wf1[(k + 2) * 512 + c];
            a3 += se[r * 64 + k + 3] * wf1[(k + 3) * 512 + c];
        }
        sz[r][cl] = bf1[c] + ((a0 + a1) + (a2 + a3));
    }
    __syncthreads();
    if (t < 64) {
        float s = 0.f, q = 0.f;
        for (int r = 0; r < 16; r++) { float v = sz[r][t]; s += v; q += v * v; }
        float mu = s * (1.f / Bb), var = q * (1.f / Bb) - mu * mu;
        float inv = rsqrtf(var + 1e-5f);
        float sc = gf1[blockIdx.x * 64 + t] * inv;
        scl[t] = sc; shf[t] = bef1[blockIdx.x * 64 + t] - sc * mu;
    }
    __syncthreads();
    #pragma unroll
    for (int q = 0; q < 4; q++) {
        int r = r0 + q * 4;
        g_fc1[r * 512 + c] = fmaxf(scl[cl] * sz[r][cl] + shf[cl], 0.f);
    }
    if (blockIdx.x == 0)
        for (int i = t; i < 1024; i += 256) out[Bb * NC + i] = se[i];
}

__global__ void __launch_bounds__(256) k_mlp2(
    const float* __restrict__ wf2, const float* __restrict__ bf2,
    const float* __restrict__ gf2, const float* __restrict__ bef2) {
    __shared__ float sf[16 * 512];
    __shared__ float sz[16][32];
    __shared__ float scl[32], shf[32];
    int t = threadIdx.x;
    for (int i = t; i < 8192; i += 256) sf[i] = g_fc1[i];
    __syncthreads();
    int cl = t & 31;
    int r0 = t >> 5;
    int c = blockIdx.x * 32 + cl;
    #pragma unroll
    for (int q = 0; q < 2; q++) {
        int r = r0 + q * 8;
        float a0 = 0.f, a1 = 0.f, a2 = 0.f, a3 = 0.f;
        for (int k = 0; k < 512; k += 4) {
            a0 += sf[r * 512 + k]     * wf2[(k)     * 256 + c];
            a1 += sf[r * 512 + k + 1] * wf2[(k + 1) * 256 + c];
            a2 += sf[r * 512 + k + 2] * wf2[(k + 2) * 256 + c];
            a3 += sf[r * 512 + k + 3] * wf2[(k + 3) * 256 + c];
        }
        sz[r][cl] = bf2[c] + ((a0 + a1) + (a2 + a3));
    }
    __syncthreads();
    if (t < 32) {
        float s = 0.f, q = 0.f;
        for (int r = 0; r < 16; r++) { float v = sz[r][t]; s += v; q += v * v; }
        float mu = s * (1.f / Bb), var = q * (1.f / Bb) - mu * mu;
        float inv = rsqrtf(var + 1e-5f);
        float sc = gf2[blockIdx.x * 32 + t] * inv;
        scl[t] = sc; shf[t] = bef2[blockIdx.x * 32 + t] - sc * mu;
    }
    __syncthreads();
    #pragma unroll
    for (int q = 0; q < 2; q++) {
        int r = r0 + q * 8;
        g_fc2[r * 256 + c] = fmaxf(scl[cl] * sz[r][cl] + shf[cl], 0.f);
    }
}

__global__ void __launch_bounds__(256) k_mlp3(
    const float* __restrict__ wf3, const float* __restrict__ bf3,
    float* __restrict__ out) {
    __shared__ float sf[16 * 256];
    __shared__ float sl[16][11];
    int t = threadIdx.x;
    for (int i = t; i < 4096; i += 256) sf[i] = g_fc2[i];
    __syncthreads();
    if (t < Bb * NC) {
        int r = t / NC, j = t % NC;
        float a0 = 0.f, a1 = 0.f, a2 = 0.f, a3 = 0.f;
        for (int k = 0; k < 256; k += 4) {
            a0 += sf[r * 256 + k]     * wf3[(k)     * NC + j];
            a1 += sf[r * 256 + k + 1] * wf3[(k + 1) * NC + j];
            a2 += sf[r * 256 + k + 2] * wf3[(k + 2) * NC + j];
            a3 += sf[r * 256 + k + 3] * wf3[(k + 3) * NC + j];
        }
        sl[r][j] = bf3[j] + ((a0 + a1) + (a2 + a3));
    }
    __syncthreads();
    if (t < Bb) {
        float m = -1e30f;
        for (int j = 0; j < NC; j++) m = fmaxf(m, sl[t][j]);
        float s = 0.f;
        for (int j = 0; j < NC; j++) s += expf(sl[t][j] - m);
        float l = m + logf(s);
        for (int j = 0; j < NC; j++) out[t * NC + j] = sl[t][j] - l;
    }
}

// ---------------- launcher ----------------
extern "C" void kernel_launch(void* const* d_in, const int* in_sizes, int n_in,
                              void* d_out, int out_size) {
    const float* x      = (const float*)d_in[0];
    const float* ea     = (const float*)d_in[1];
    const float* w_edge = (const float*)d_in[2];
    const float* b_edge = (const float*)d_in[3];
    const float* w1  = (const float*)d_in[4];  const float* b1  = (const float*)d_in[5];
    const float* g1  = (const float*)d_in[6];  const float* be1 = (const float*)d_in[7];
    const float* w2  = (const float*)d_in[8];  const float* b2  = (const float*)d_in[9];
    const float* g2  = (const float*)d_in[10]; const float* be2 = (const float*)d_in[11];
    const float* w3  = (const float*)d_in[12]; const float* b3  = (const float*)d_in[13];
    const float* g3  = (const float*)d_in[14]; const float* be3 = (const float*)d_in[15];
    const float* wf1 = (const float*)d_in[16]; const float* bf1 = (const float*)d_in[17];
    const float* gf1 = (const float*)d_in[18]; const float* bef1= (const float*)d_in[19];
    const float* wf2 = (const float*)d_in[20]; const float* bf2 = (const float*)d_in[21];
    const float* gf2 = (const float*)d_in[22]; const float* bef2= (const float*)d_in[23];
    const float* wf3 = (const float*)d_in[24]; const float* bf3 = (const float*)d_in[25];
    const int*   ei    = (const int*)d_in[26];
    const int*   batch = (const int*)d_in[27];
    float* out = (float*)d_out;

    float *x16, *z1, *z2, *z3, *sum, *sq;
    cudaGetSymbolAddress((void**)&x16, g_x16);
    cudaGetSymbolAddress((void**)&z1,  g_z1);
    cudaGetSymbolAddress((void**)&z2,  g_z2);
    cudaGetSymbolAddress((void**)&z3,  g_z3);
    cudaGetSymbolAddress((void**)&sum, g_sum);
    cudaGetSymbolAddress((void**)&sq,  g_sq);

    const int T = 256;
    k_init<<<(Nn * 16 + T - 1) / T, T>>>(x);
    k_edge<<<(Ee + T - 1) / T, T>>>(ea, w_edge, b_edge, ei);
    k_scan<<<1, 1024>>>();
    k_scatter<<<(Ee + T - 1) / T, T>>>(ei);

    constexpr int LG = 768;  // 768 blocks * 8 warps * 2 rows = 12288
    k_layer<16, FIN, Hh, false, LG><<<LG, T>>>(x16, w1, b1, nullptr, nullptr,
                                               nullptr, nullptr, z1, sum, sq);
    k_layer<Hh, Hh, H2, true, LG><<<LG, T>>>(z1, w2, b2, g1, be1, sum, sq,
                                             z2, sum + 64, sq + 64);
    k_layer<H2, H2, H2, true, LG><<<LG, T>>>(z2, w3, b3, g2, be2, sum + 64, sq + 64,
                                             z3, sum + 128, sq + 128);

    k_pool<<<96, T>>>(z3, batch, g3, be3);

    k_mlp1<<<8, T>>>(wf1, bf1, gf1, bef1, out);
    k_mlp2<<<8, T>>>(wf2, bf2, gf2, bef2);
    k_mlp3<<<1, T>>>(wf3, bf3, out);
}